// round 1
// baseline (speedup 1.0000x reference)
#include <cuda_runtime.h>
#include <math.h>

namespace {

constexpr int BS    = 16;
constexpr int NGT   = 20;
constexpr int NA    = 3;
constexpr int GS    = 76;
constexpr int NC    = 80;
constexpr int NATTR = 5 + NC;           // 85
constexpr int NTOT  = BS * NGT;         // 320 ground truths
constexpr int PLANE = GS * GS;          // 5776
constexpr int TOTAL_CELLS = BS * NA * GS * GS;  // 277248

__device__ __forceinline__ float sigmoidf(float v) {
    return 1.0f / (1.0f + expf(-v));
}

// One block, NTOT threads: thread t handles ground truth (b = t/NGT, g = t%NGT).
__global__ void yolo_loss_kernel(const float* __restrict__ x,
                                 const float* __restrict__ yt,
                                 float* __restrict__ out)
{
    // anchors / stride, stride = 608/76 = 8
    const float ANCW[3] = {10.0f / 8.0f, 16.0f / 8.0f, 33.0f / 8.0f};
    const float ANCH[3] = {13.0f / 8.0f, 30.0f / 8.0f, 23.0f / 8.0f};

    __shared__ int   s_lin[NTOT];
    __shared__ float s_red[7][16];   // per-warp partial sums (10 warps used)

    const int t = threadIdx.x;       // 0..319
    const int b = t / NGT;

    // ---- per-GT geometry ----
    const float* g = yt + (size_t)t * 5;
    const float gx = g[0] * (float)GS;
    const float gy = g[1] * (float)GS;
    const float gw = g[2] * (float)GS;
    const float gh = g[3] * (float)GS;
    const int   cls = (int)g[4];

    int gi = (int)gx; gi = min(max(gi, 0), GS - 1);
    int gj = (int)gy; gj = min(max(gj, 0), GS - 1);

    // GT box corners (mirror reference _xywh2xyxy exactly)
    const float gx1 = gx - gw / 2.0f, gy1 = gy - gh / 2.0f;
    const float gx2 = gx + gw / 2.0f, gy2 = gy + gh / 2.0f;
    const float area_g = (gx2 - gx1) * (gy2 - gy1);

    // ---- best anchor by IoU (argmax -> first max wins, so strict >) ----
    float best_iou = -INFINITY;
    int   best_a   = 0;
    #pragma unroll
    for (int a = 0; a < NA; a++) {
        const float* xp = x + (size_t)(b * NA + a) * NATTR * PLANE
                            + (size_t)gj * GS + gi;
        const float tx = xp[0];
        const float ty = xp[PLANE];
        const float tw = xp[2 * PLANE];
        const float th = xp[3 * PLANE];

        const float bx = sigmoidf(tx) + (float)gi;
        const float by = sigmoidf(ty) + (float)gj;
        const float bw = expf(tw) * ANCW[a];
        const float bh = expf(th) * ANCH[a];

        const float px1 = bx - bw / 2.0f, py1 = by - bh / 2.0f;
        const float px2 = bx + bw / 2.0f, py2 = by + bh / 2.0f;

        const float ix1 = fmaxf(px1, gx1), iy1 = fmaxf(py1, gy1);
        const float ix2 = fminf(px2, gx2), iy2 = fminf(py2, gy2);
        const float inter = fmaxf(ix2 - ix1, 0.0f) * fmaxf(iy2 - iy1, 0.0f);
        const float area_p = (px2 - px1) * (py2 - py1);
        const float iou = inter / (area_p + area_g - inter + 1e-16f);

        if (iou > best_iou) { best_iou = iou; best_a = a; }
    }

    // ---- duplicate resolution: JAX scatter .set => last flat index wins ----
    const int lin = ((b * NA + best_a) * GS + gj) * GS + gi;
    s_lin[t] = lin;
    __syncthreads();
    int winner = 1;
    for (int u = t + 1; u < NTOT; u++) {
        if (s_lin[u] == lin) { winner = 0; break; }
    }

    // ---- winner loss contributions ----
    float lx = 0.f, ly = 0.f, lw = 0.f, lh = 0.f, lcls = 0.f, lconf = 0.f;
    if (winner) {
        const float* xp = x + (size_t)(b * NA + best_a) * NATTR * PLANE
                            + (size_t)gj * GS + gi;
        const float tx = xp[0];
        const float ty = xp[PLANE];
        const float tw = xp[2 * PLANE];
        const float th = xp[3 * PLANE];
        const float cf = xp[4 * PLANE];

        const float dx = sigmoidf(tx) - (gx - (float)gi);
        const float dy = sigmoidf(ty) - (gy - (float)gj);
        const float dw = tw - logf(gw / ANCW[best_a]);
        const float dh = th - logf(gh / ANCH[best_a]);
        lx = dx * dx; ly = dy * dy; lw = dw * dw; lh = dh * dh;

        const float dc = sigmoidf(cf) * 5.0f - best_iou * 5.0f;
        lconf = dc * dc;

        // logsumexp over the 80 class logits minus picked logit
        float v[NC];
        float m = -INFINITY;
        #pragma unroll
        for (int k = 0; k < NC; k++) {
            v[k] = xp[(size_t)(5 + k) * PLANE];
            m = fmaxf(m, v[k]);
        }
        float s = 0.0f;
        #pragma unroll
        for (int k = 0; k < NC; k++) s += expf(v[k] - m);
        lcls = (m + logf(s)) - v[cls];
    }

    // ---- block reduction of {lx,ly,lw,lh,lcls,lconf,n_obj} ----
    float vals[7] = {lx, ly, lw, lh, lcls, lconf, (float)winner};
    #pragma unroll
    for (int i = 0; i < 7; i++) {
        float v2 = vals[i];
        #pragma unroll
        for (int o = 16; o > 0; o >>= 1)
            v2 += __shfl_down_sync(0xffffffffu, v2, o);
        vals[i] = v2;
    }
    const int wid = t >> 5, lane = t & 31;
    if (lane == 0) {
        #pragma unroll
        for (int i = 0; i < 7; i++) s_red[i][wid] = vals[i];
    }
    __syncthreads();

    if (t == 0) {
        float tot[7];
        #pragma unroll
        for (int i = 0; i < 7; i++) {
            float s = 0.0f;
            for (int w = 0; w < NTOT / 32; w++) s += s_red[i][w];
            tot[i] = s;
        }
        const int n_obj = (int)(tot[6] + 0.5f);
        // background cells each contribute logsumexp(zeros(80)) = log(80)
        const double cls_bg =
            (double)(TOTAL_CELLS - n_obj) * (double)logf(80.0f);

        out[0] = tot[0];                          // loss_x
        out[1] = tot[1];                          // loss_y
        out[2] = tot[2];                          // loss_w
        out[3] = tot[3];                          // loss_h
        out[4] = (float)(cls_bg + (double)tot[4]);// loss_cls
        out[5] = tot[5];                          // loss_conf
    }
}

} // namespace

extern "C" void kernel_launch(void* const* d_in, const int* in_sizes, int n_in,
                              void* d_out, int out_size)
{
    const float* x  = (const float*)d_in[0];   // (16, 255, 76, 76) f32
    const float* yt = (const float*)d_in[1];   // (16, 20, 5) f32
    float* out = (float*)d_out;                // 6 floats

    yolo_loss_kernel<<<1, NTOT>>>(x, yt, out);
}

// round 2
// speedup vs baseline: 3.9437x; 3.9437x over previous
#include <cuda_runtime.h>
#include <math.h>

namespace {

constexpr int BS    = 16;
constexpr int NGT   = 20;
constexpr int NA    = 3;
constexpr int GS    = 76;
constexpr int NC    = 80;
constexpr int NATTR = 5 + NC;           // 85
constexpr int NTOT  = BS * NGT;         // 320 ground truths
constexpr int PLANE = GS * GS;          // 5776
constexpr int TOTAL_CELLS = BS * NA * GS * GS;  // 277248

struct GtEntry {
    int   lin;       // flat cell index, or -1 if not a winner
    int   cls;       // class label
    float txT, tyT;  // x/y targets (gx - gi, gy - gj)
    float twT, thT;  // w/h targets (log(gw/anchw), log(gh/anch))
    float best_iou;
};

__device__ GtEntry g_ent[NTOT];

__device__ __forceinline__ float sigmoidf(float v) {
    return 1.0f / (1.0f + expf(-v));
}

// ---------------------------------------------------------------------------
// Kernel A: per-GT geometry, best-anchor argmax, duplicate resolution.
// One block, NTOT threads. Also initializes out[].
// ---------------------------------------------------------------------------
__global__ void yolo_prep_kernel(const float* __restrict__ x,
                                 const float* __restrict__ yt,
                                 float* __restrict__ out)
{
    const float ANCW[3] = {10.0f / 8.0f, 16.0f / 8.0f, 33.0f / 8.0f};
    const float ANCH[3] = {13.0f / 8.0f, 30.0f / 8.0f, 23.0f / 8.0f};

    __shared__ int s_lin[NTOT];
    __shared__ int s_nobj[16];

    const int t = threadIdx.x;       // 0..319
    const int b = t / NGT;

    const float* g = yt + (size_t)t * 5;
    const float gx = g[0] * (float)GS;
    const float gy = g[1] * (float)GS;
    const float gw = g[2] * (float)GS;
    const float gh = g[3] * (float)GS;
    const int   cls = (int)g[4];

    int gi = (int)gx; gi = min(max(gi, 0), GS - 1);
    int gj = (int)gy; gj = min(max(gj, 0), GS - 1);

    const float gx1 = gx - gw / 2.0f, gy1 = gy - gh / 2.0f;
    const float gx2 = gx + gw / 2.0f, gy2 = gy + gh / 2.0f;
    const float area_g = (gx2 - gx1) * (gy2 - gy1);

    // Issue all 12 anchor-probe loads up front (independent -> MLP 12)
    float tx_[NA], ty_[NA], tw_[NA], th_[NA];
    #pragma unroll
    for (int a = 0; a < NA; a++) {
        const float* xp = x + (size_t)(b * NA + a) * NATTR * PLANE
                            + (size_t)gj * GS + gi;
        tx_[a] = xp[0];
        ty_[a] = xp[PLANE];
        tw_[a] = xp[2 * PLANE];
        th_[a] = xp[3 * PLANE];
    }

    float best_iou = -INFINITY;
    int   best_a   = 0;
    #pragma unroll
    for (int a = 0; a < NA; a++) {
        const float bx = sigmoidf(tx_[a]) + (float)gi;
        const float by = sigmoidf(ty_[a]) + (float)gj;
        const float bw = expf(tw_[a]) * ANCW[a];
        const float bh = expf(th_[a]) * ANCH[a];

        const float px1 = bx - bw / 2.0f, py1 = by - bh / 2.0f;
        const float px2 = bx + bw / 2.0f, py2 = by + bh / 2.0f;

        const float ix1 = fmaxf(px1, gx1), iy1 = fmaxf(py1, gy1);
        const float ix2 = fminf(px2, gx2), iy2 = fminf(py2, gy2);
        const float inter = fmaxf(ix2 - ix1, 0.0f) * fmaxf(iy2 - iy1, 0.0f);
        const float area_p = (px2 - px1) * (py2 - py1);
        const float iou = inter / (area_p + area_g - inter + 1e-16f);

        if (iou > best_iou) { best_iou = iou; best_a = a; }
    }

    // Duplicate resolution: JAX scatter .set -> last flat index wins.
    const int lin = ((b * NA + best_a) * GS + gj) * GS + gi;
    s_lin[t] = lin;
    __syncthreads();
    int winner = 1;
    for (int u = t + 1; u < NTOT; u++) {
        if (s_lin[u] == lin) { winner = 0; break; }
    }

    GtEntry e;
    e.lin = winner ? lin : -1;
    e.cls = cls;
    e.txT = gx - (float)gi;
    e.tyT = gy - (float)gj;
    e.twT = logf(gw / ANCW[best_a]);
    e.thT = logf(gh / ANCH[best_a]);
    e.best_iou = best_iou;
    g_ent[t] = e;

    // count winners (warp ballot + smem)
    unsigned bal = __ballot_sync(0xffffffffu, winner);
    const int wid = t >> 5, lane = t & 31;
    if (lane == 0) s_nobj[wid] = __popc(bal);
    __syncthreads();

    if (t == 0) {
        int n_obj = 0;
        for (int w = 0; w < NTOT / 32; w++) n_obj += s_nobj[w];
        out[0] = 0.0f; out[1] = 0.0f; out[2] = 0.0f; out[3] = 0.0f;
        out[4] = (float)((double)(TOTAL_CELLS - n_obj) * (double)logf(80.0f));
        out[5] = 0.0f;
    }
}

// ---------------------------------------------------------------------------
// Kernel B: one warp per GT. Lanes cooperatively load the 85 attributes of
// the winning cell, warp-reduce logsumexp, lane 0 accumulates losses.
// ---------------------------------------------------------------------------
__global__ void yolo_loss_kernel(const float* __restrict__ x,
                                 float* __restrict__ out)
{
    const int gwarp = (blockIdx.x * blockDim.x + threadIdx.x) >> 5;
    const int lane  = threadIdx.x & 31;
    if (gwarp >= NTOT) return;

    const GtEntry e = g_ent[gwarp];
    if (e.lin < 0) return;

    const float* base = x + (size_t)(e.lin / PLANE) * NATTR * PLANE
                          + (e.lin % PLANE);

    // lanes 0..4 load tx,ty,tw,th,conf ; lane 5 loads the picked class logit
    float attr = 0.0f;
    if (lane < 5)       attr = base[(size_t)lane * PLANE];
    else if (lane == 5) attr = base[(size_t)(5 + e.cls) * PLANE];

    // class logits: lane handles k = lane, lane+32, lane+64
    float v0 = base[(size_t)(5 + lane) * PLANE];
    float v1 = base[(size_t)(5 + lane + 32) * PLANE];
    float v2 = (lane < NC - 64) ? base[(size_t)(5 + lane + 64) * PLANE]
                                : -INFINITY;

    // warp max
    float m = fmaxf(fmaxf(v0, v1), v2);
    #pragma unroll
    for (int o = 16; o > 0; o >>= 1)
        m = fmaxf(m, __shfl_xor_sync(0xffffffffu, m, o));

    // warp sum of exp
    float s = expf(v0 - m) + expf(v1 - m) +
              ((lane < NC - 64) ? expf(v2 - m) : 0.0f);
    #pragma unroll
    for (int o = 16; o > 0; o >>= 1)
        s += __shfl_xor_sync(0xffffffffu, s, o);

    const float tx = __shfl_sync(0xffffffffu, attr, 0);
    const float ty = __shfl_sync(0xffffffffu, attr, 1);
    const float tw = __shfl_sync(0xffffffffu, attr, 2);
    const float th = __shfl_sync(0xffffffffu, attr, 3);
    const float cf = __shfl_sync(0xffffffffu, attr, 4);
    const float pk = __shfl_sync(0xffffffffu, attr, 5);

    if (lane == 0) {
        const float dx = sigmoidf(tx) - e.txT;
        const float dy = sigmoidf(ty) - e.tyT;
        const float dw = tw - e.twT;
        const float dh = th - e.thT;
        const float dc = sigmoidf(cf) * 5.0f - e.best_iou * 5.0f;
        const float lcls = (m + logf(s)) - pk;

        atomicAdd(&out[0], dx * dx);
        atomicAdd(&out[1], dy * dy);
        atomicAdd(&out[2], dw * dw);
        atomicAdd(&out[3], dh * dh);
        atomicAdd(&out[4], lcls);
        atomicAdd(&out[5], dc * dc);
    }
}

} // namespace

extern "C" void kernel_launch(void* const* d_in, const int* in_sizes, int n_in,
                              void* d_out, int out_size)
{
    const float* x  = (const float*)d_in[0];   // (16, 255, 76, 76) f32
    const float* yt = (const float*)d_in[1];   // (16, 20, 5) f32
    float* out = (float*)d_out;                // 6 floats

    yolo_prep_kernel<<<1, NTOT>>>(x, yt, out);
    // 320 warps: 40 blocks x 256 threads (8 warps each)
    yolo_loss_kernel<<<40, 256>>>(x, out);
}

// round 3
// speedup vs baseline: 8.0000x; 2.0286x over previous
#include <cuda_runtime.h>
#include <math.h>

namespace {

constexpr int BS    = 16;
constexpr int NGT   = 20;
constexpr int NA    = 3;
constexpr int GS    = 76;
constexpr int NC    = 80;
constexpr int NATTR = 5 + NC;           // 85
constexpr int NTOT  = BS * NGT;         // 320 ground truths
constexpr int PLANE = GS * GS;          // 5776
constexpr int TOTAL_CELLS = BS * NA * GS * GS;  // 277248

constexpr int NBLK   = 20;
constexpr int NTHR   = 512;             // 16 warps -> 16 GTs per block
constexpr int WARPS  = NTHR / 32;

__device__ float g_acc[7];              // zero-init; reset by last block
__device__ unsigned int g_tickets;      // zero-init; reset by last block

__device__ __forceinline__ float sigmoidf(float v) {
    return 1.0f / (1.0f + expf(-v));
}

__global__ __launch_bounds__(NTHR)
void yolo_fused_kernel(const float* __restrict__ x,
                       const float* __restrict__ yt,
                       float* __restrict__ out)
{
    const float ANCW[3] = {10.0f / 8.0f, 16.0f / 8.0f, 33.0f / 8.0f};
    const float ANCH[3] = {13.0f / 8.0f, 30.0f / 8.0f, 23.0f / 8.0f};

    __shared__ int   s_lin[NTOT];
    __shared__ int   s_cls[NTOT];
    __shared__ float s_txT[NTOT], s_tyT[NTOT];
    __shared__ float s_twT[NTOT], s_thT[NTOT];
    __shared__ float s_iou[NTOT];
    __shared__ float s_red[7][WARPS];

    const int t    = threadIdx.x;
    const int wid  = t >> 5;
    const int lane = t & 31;

    // ---------------- Phase 1: every block computes ALL 320 GT entries ----
    if (t < NTOT) {
        const int b = t / NGT;
        const float* g = yt + (size_t)t * 5;
        const float gx = g[0] * (float)GS;
        const float gy = g[1] * (float)GS;
        const float gw = g[2] * (float)GS;
        const float gh = g[3] * (float)GS;
        const int   cls = (int)g[4];

        int gi = (int)gx; gi = min(max(gi, 0), GS - 1);
        int gj = (int)gy; gj = min(max(gj, 0), GS - 1);

        const float gx1 = gx - gw / 2.0f, gy1 = gy - gh / 2.0f;
        const float gx2 = gx + gw / 2.0f, gy2 = gy + gh / 2.0f;
        const float area_g = (gx2 - gx1) * (gy2 - gy1);

        // 12 independent probe loads up front (MLP 12)
        float tx_[NA], ty_[NA], tw_[NA], th_[NA];
        #pragma unroll
        for (int a = 0; a < NA; a++) {
            const float* xp = x + (size_t)(b * NA + a) * NATTR * PLANE
                                + (size_t)gj * GS + gi;
            tx_[a] = xp[0];
            ty_[a] = xp[PLANE];
            tw_[a] = xp[2 * PLANE];
            th_[a] = xp[3 * PLANE];
        }

        float best_iou = -INFINITY;
        int   best_a   = 0;
        #pragma unroll
        for (int a = 0; a < NA; a++) {
            const float bx = sigmoidf(tx_[a]) + (float)gi;
            const float by = sigmoidf(ty_[a]) + (float)gj;
            const float bw = expf(tw_[a]) * ANCW[a];
            const float bh = expf(th_[a]) * ANCH[a];

            const float px1 = bx - bw / 2.0f, py1 = by - bh / 2.0f;
            const float px2 = bx + bw / 2.0f, py2 = by + bh / 2.0f;

            const float ix1 = fmaxf(px1, gx1), iy1 = fmaxf(py1, gy1);
            const float ix2 = fminf(px2, gx2), iy2 = fminf(py2, gy2);
            const float inter = fmaxf(ix2 - ix1, 0.0f) * fmaxf(iy2 - iy1, 0.0f);
            const float area_p = (px2 - px1) * (py2 - py1);
            const float iou = inter / (area_p + area_g - inter + 1e-16f);

            if (iou > best_iou) { best_iou = iou; best_a = a; }
        }

        s_lin[t] = ((b * NA + best_a) * GS + gj) * GS + gi;
        s_cls[t] = cls;
        s_txT[t] = gx - (float)gi;
        s_tyT[t] = gy - (float)gj;
        s_twT[t] = logf(gw / ANCW[best_a]);
        s_thT[t] = logf(gh / ANCH[best_a]);
        s_iou[t] = best_iou;
    }
    __syncthreads();

    // ---------------- Phase 2: warp w handles GT gidx ---------------------
    const int gidx = blockIdx.x * WARPS + wid;   // 0..319 (20 blocks * 16)

    float lx = 0.f, ly = 0.f, lw = 0.f, lh = 0.f;
    float lcls = 0.f, lconf = 0.f, fwin = 0.f;

    {
        const int lin = s_lin[gidx];

        // cooperative duplicate scan: JAX scatter -> last flat index wins
        int dup = 0;
        for (int u = gidx + 1 + lane; u < NTOT; u += 32)
            dup |= (s_lin[u] == lin);
        const unsigned dmask = __ballot_sync(0xffffffffu, dup);

        if (dmask == 0u) {   // winner
            fwin = 1.0f;
            const int cls = s_cls[gidx];
            const float* base = x + (size_t)(lin / PLANE) * NATTR * PLANE
                                  + (lin % PLANE);

            float attr = 0.0f;
            if (lane < 5)       attr = base[(size_t)lane * PLANE];
            else if (lane == 5) attr = base[(size_t)(5 + cls) * PLANE];

            float v0 = base[(size_t)(5 + lane) * PLANE];
            float v1 = base[(size_t)(5 + lane + 32) * PLANE];
            float v2 = (lane < NC - 64) ? base[(size_t)(5 + lane + 64) * PLANE]
                                        : -INFINITY;

            float m = fmaxf(fmaxf(v0, v1), v2);
            #pragma unroll
            for (int o = 16; o > 0; o >>= 1)
                m = fmaxf(m, __shfl_xor_sync(0xffffffffu, m, o));

            float s = expf(v0 - m) + expf(v1 - m) +
                      ((lane < NC - 64) ? expf(v2 - m) : 0.0f);
            #pragma unroll
            for (int o = 16; o > 0; o >>= 1)
                s += __shfl_xor_sync(0xffffffffu, s, o);

            const float tx = __shfl_sync(0xffffffffu, attr, 0);
            const float ty = __shfl_sync(0xffffffffu, attr, 1);
            const float tw = __shfl_sync(0xffffffffu, attr, 2);
            const float th = __shfl_sync(0xffffffffu, attr, 3);
            const float cf = __shfl_sync(0xffffffffu, attr, 4);
            const float pk = __shfl_sync(0xffffffffu, attr, 5);

            const float dx = sigmoidf(tx) - s_txT[gidx];
            const float dy = sigmoidf(ty) - s_tyT[gidx];
            const float dw = tw - s_twT[gidx];
            const float dh = th - s_thT[gidx];
            const float dc = sigmoidf(cf) * 5.0f - s_iou[gidx] * 5.0f;

            lx = dx * dx; ly = dy * dy; lw = dw * dw; lh = dh * dh;
            lconf = dc * dc;
            lcls  = (m + logf(s)) - pk;
        }
    }

    // ---------------- Phase 3: block reduce + last-block finalize ----------
    if (lane == 0) {
        s_red[0][wid] = lx;   s_red[1][wid] = ly;
        s_red[2][wid] = lw;   s_red[3][wid] = lh;
        s_red[4][wid] = lcls; s_red[5][wid] = lconf;
        s_red[6][wid] = fwin;
    }
    __syncthreads();

    if (t == 0) {
        float tot[7];
        #pragma unroll
        for (int i = 0; i < 7; i++) {
            float s = 0.0f;
            for (int w = 0; w < WARPS; w++) s += s_red[i][w];
            tot[i] = s;
            atomicAdd(&g_acc[i], s);
        }
        __threadfence();
        const unsigned old = atomicAdd(&g_tickets, 1u);
        if (old == NBLK - 1) {
            // last block: compose output, reset scratch for next graph replay
            volatile float* acc = g_acc;
            const float ax = acc[0], ay = acc[1], aw = acc[2], ah = acc[3];
            const float acls = acc[4], aconf = acc[5], awin = acc[6];
            const int n_obj = (int)(awin + 0.5f);

            out[0] = ax;  out[1] = ay;  out[2] = aw;  out[3] = ah;
            out[4] = (float)((double)(TOTAL_CELLS - n_obj) * (double)logf(80.0f)
                             + (double)acls);
            out[5] = aconf;

            #pragma unroll
            for (int i = 0; i < 7; i++) g_acc[i] = 0.0f;
            __threadfence();
            g_tickets = 0u;
        }
    }
}

} // namespace

extern "C" void kernel_launch(void* const* d_in, const int* in_sizes, int n_in,
                              void* d_out, int out_size)
{
    const float* x  = (const float*)d_in[0];   // (16, 255, 76, 76) f32
    const float* yt = (const float*)d_in[1];   // (16, 20, 5) f32
    float* out = (float*)d_out;                // 6 floats

    yolo_fused_kernel<<<NBLK, NTHR>>>(x, yt, out);
}

// round 4
// speedup vs baseline: 8.1481x; 1.0185x over previous
#include <cuda_runtime.h>
#include <math.h>

namespace {

constexpr int BS    = 16;
constexpr int NGT   = 20;
constexpr int NA    = 3;
constexpr int GS    = 76;
constexpr int NC    = 80;
constexpr int NATTR = 5 + NC;           // 85
constexpr int NTOT  = BS * NGT;         // 320 ground truths
constexpr int PLANE = GS * GS;          // 5776
constexpr int TOTAL_CELLS = BS * NA * GS * GS;  // 277248

constexpr int WARPS = 8;                // GTs (warps) per block
constexpr int NBLK  = NTOT / WARPS;     // 40 blocks
constexpr int NTHR  = WARPS * 32;       // 256 threads

__device__ int          g_lin_arr[NTOT];
__device__ unsigned int g_count;        // zero-init; reset by last block
__device__ float        g_acc[7];       // zero-init; reset by last block
__device__ unsigned int g_tickets;      // zero-init; reset by last block

__device__ __forceinline__ float sigmoidf(float v) {
    return 1.0f / (1.0f + expf(-v));
}

__global__ __launch_bounds__(NTHR)
void yolo_fused_kernel(const float* __restrict__ x,
                       const float* __restrict__ yt,
                       float* __restrict__ out)
{
    __shared__ float s_red[7][WARPS];

    const int t    = threadIdx.x;
    const int wid  = t >> 5;
    const int lane = t & 31;
    const int g    = blockIdx.x * WARPS + wid;   // GT index 0..319
    const int b    = g / NGT;

    // ---- GT geometry (broadcast loads, all lanes same address) -----------
    const float* gp = yt + (size_t)g * 5;
    const float gx = gp[0] * (float)GS;
    const float gy = gp[1] * (float)GS;
    const float gw = gp[2] * (float)GS;
    const float gh = gp[3] * (float)GS;
    const int   cls = (int)gp[4];

    int gi = (int)gx; gi = min(max(gi, 0), GS - 1);
    int gj = (int)gy; gj = min(max(gj, 0), GS - 1);

    const float gx1 = gx - gw / 2.0f, gy1 = gy - gh / 2.0f;
    const float gx2 = gx + gw / 2.0f, gy2 = gy + gh / 2.0f;
    const float area_g = (gx2 - gx1) * (gy2 - gy1);

    // ---- anchor probes: lane a (a<3) handles anchor a --------------------
    const float ancw = (lane == 0) ? 1.25f : (lane == 1) ? 2.0f : 4.125f;
    const float anch = (lane == 0) ? 1.625f : (lane == 1) ? 3.75f : 2.875f;

    float iou = -INFINITY;
    if (lane < NA) {
        const float* xp = x + (size_t)(b * NA + lane) * NATTR * PLANE
                            + (size_t)gj * GS + gi;
        const float txp = xp[0];
        const float typ = xp[PLANE];
        const float twp = xp[2 * PLANE];
        const float thp = xp[3 * PLANE];

        const float bx = sigmoidf(txp) + (float)gi;
        const float by = sigmoidf(typ) + (float)gj;
        const float bw = expf(twp) * ancw;
        const float bh = expf(thp) * anch;

        const float px1 = bx - bw / 2.0f, py1 = by - bh / 2.0f;
        const float px2 = bx + bw / 2.0f, py2 = by + bh / 2.0f;

        const float ix1 = fmaxf(px1, gx1), iy1 = fmaxf(py1, gy1);
        const float ix2 = fminf(px2, gx2), iy2 = fminf(py2, gy2);
        const float inter = fmaxf(ix2 - ix1, 0.0f) * fmaxf(iy2 - iy1, 0.0f);
        const float area_p = (px2 - px1) * (py2 - py1);
        iou = inter / (area_p + area_g - inter + 1e-16f);
    }

    // argmax over the 3 anchors (first max wins -> strict >), replicated
    const float i0 = __shfl_sync(0xffffffffu, iou, 0);
    const float i1 = __shfl_sync(0xffffffffu, iou, 1);
    const float i2 = __shfl_sync(0xffffffffu, iou, 2);
    int   best_a   = 0;
    float best_iou = i0;
    if (i1 > best_iou) { best_iou = i1; best_a = 1; }
    if (i2 > best_iou) { best_iou = i2; best_a = 2; }

    const int lin = ((b * NA + best_a) * GS + gj) * GS + gi;

    // ---- issue phase-2 loads NOW (independent of the exchange) -----------
    const float* base = x + (size_t)(lin / PLANE) * NATTR * PLANE
                          + (lin % PLANE);
    float attr = 0.0f;
    if (lane < 5)       attr = base[(size_t)lane * PLANE];
    else if (lane == 5) attr = base[(size_t)(5 + cls) * PLANE];

    const float v0 = base[(size_t)(5 + lane) * PLANE];
    const float v1 = base[(size_t)(5 + lane + 32) * PLANE];
    const float v2 = (lane < NC - 64) ? base[(size_t)(5 + lane + 64) * PLANE]
                                      : -INFINITY;

    // ---- publish lin, then spin until all 320 warps have published -------
    if (lane == 0) {
        g_lin_arr[g] = lin;
        __threadfence();
        atomicAdd(&g_count, 1u);
    }
    while (*(volatile unsigned int*)&g_count < (unsigned)NTOT) { }
    __threadfence();

    // ---- dedup: JAX scatter .set -> last flat index wins -----------------
    int dup = 0;
    for (int u = g + 1 + lane; u < NTOT; u += 32)
        dup |= (g_lin_arr[u] == lin);
    const unsigned dmask = __ballot_sync(0xffffffffu, dup);

    float lx = 0.f, ly = 0.f, lw = 0.f, lh = 0.f;
    float lcls = 0.f, lconf = 0.f, fwin = 0.f;

    if (dmask == 0u) {   // winner
        fwin = 1.0f;

        // warp logsumexp over the 80 class logits
        float m = fmaxf(fmaxf(v0, v1), v2);
        #pragma unroll
        for (int o = 16; o > 0; o >>= 1)
            m = fmaxf(m, __shfl_xor_sync(0xffffffffu, m, o));

        float s = expf(v0 - m) + expf(v1 - m) +
                  ((lane < NC - 64) ? expf(v2 - m) : 0.0f);
        #pragma unroll
        for (int o = 16; o > 0; o >>= 1)
            s += __shfl_xor_sync(0xffffffffu, s, o);

        const float tx = __shfl_sync(0xffffffffu, attr, 0);
        const float ty = __shfl_sync(0xffffffffu, attr, 1);
        const float tw = __shfl_sync(0xffffffffu, attr, 2);
        const float th = __shfl_sync(0xffffffffu, attr, 3);
        const float cf = __shfl_sync(0xffffffffu, attr, 4);
        const float pk = __shfl_sync(0xffffffffu, attr, 5);

        const float ancwB = (best_a == 0) ? 1.25f : (best_a == 1) ? 2.0f : 4.125f;
        const float anchB = (best_a == 0) ? 1.625f : (best_a == 1) ? 3.75f : 2.875f;

        const float dx = sigmoidf(tx) - (gx - (float)gi);
        const float dy = sigmoidf(ty) - (gy - (float)gj);
        const float dw = tw - logf(gw / ancwB);
        const float dh = th - logf(gh / anchB);
        const float dc = sigmoidf(cf) * 5.0f - best_iou * 5.0f;

        lx = dx * dx; ly = dy * dy; lw = dw * dw; lh = dh * dh;
        lconf = dc * dc;
        lcls  = (m + logf(s)) - pk;
    }

    // ---- block reduction + last-block finalize ---------------------------
    if (lane == 0) {
        s_red[0][wid] = lx;   s_red[1][wid] = ly;
        s_red[2][wid] = lw;   s_red[3][wid] = lh;
        s_red[4][wid] = lcls; s_red[5][wid] = lconf;
        s_red[6][wid] = fwin;
    }
    __syncthreads();

    if (t == 0) {
        #pragma unroll
        for (int i = 0; i < 7; i++) {
            float s = 0.0f;
            for (int w = 0; w < WARPS; w++) s += s_red[i][w];
            atomicAdd(&g_acc[i], s);
        }
        __threadfence();
        const unsigned old = atomicAdd(&g_tickets, 1u);
        if (old == NBLK - 1) {
            volatile float* acc = g_acc;
            const float ax = acc[0], ay = acc[1], aw = acc[2], ah = acc[3];
            const float acls = acc[4], aconf = acc[5], awin = acc[6];
            const int n_obj = (int)(awin + 0.5f);

            out[0] = ax;  out[1] = ay;  out[2] = aw;  out[3] = ah;
            out[4] = (float)((double)(TOTAL_CELLS - n_obj) * (double)logf(80.0f)
                             + (double)acls);
            out[5] = aconf;

            // reset scratch for the next graph replay
            #pragma unroll
            for (int i = 0; i < 7; i++) g_acc[i] = 0.0f;
            g_tickets = 0u;
            g_count   = 0u;
            __threadfence();
        }
    }
}

} // namespace

extern "C" void kernel_launch(void* const* d_in, const int* in_sizes, int n_in,
                              void* d_out, int out_size)
{
    const float* x  = (const float*)d_in[0];   // (16, 255, 76, 76) f32
    const float* yt = (const float*)d_in[1];   // (16, 20, 5) f32
    float* out = (float*)d_out;                // 6 floats

    yolo_fused_kernel<<<NBLK, NTHR>>>(x, yt, out);
}

// round 5
// speedup vs baseline: 9.6250x; 1.1813x over previous
#include <cuda_runtime.h>
#include <math.h>

namespace {

constexpr int BS    = 16;
constexpr int NGT   = 20;
constexpr int NA    = 3;
constexpr int GS    = 76;
constexpr int NC    = 80;
constexpr int NATTR = 5 + NC;           // 85
constexpr int PLANE = GS * GS;          // 5776
constexpr int TOTAL_CELLS = BS * NA * GS * GS;  // 277248

constexpr int NBLK  = BS;               // one block per batch image
constexpr int WARPS = NGT;              // one warp per ground truth
constexpr int NTHR  = WARPS * 32;       // 640 threads

__device__ float        g_acc[7];       // zero-init; reset by last block
__device__ unsigned int g_tickets;     // zero-init; reset by last block

__device__ __forceinline__ float sigmoidf(float v) {
    return 1.0f / (1.0f + expf(-v));
}

__global__ __launch_bounds__(NTHR)
void yolo_fused_kernel(const float* __restrict__ x,
                       const float* __restrict__ yt,
                       float* __restrict__ out)
{
    __shared__ int   s_lin[NGT];
    __shared__ float s_red[7][WARPS];

    const int t    = threadIdx.x;
    const int wid  = t >> 5;            // GT within batch: 0..19
    const int lane = t & 31;
    const int b    = blockIdx.x;        // batch: 0..15

    // ---- GT geometry (broadcast load, all lanes same address) ------------
    const float* gp = yt + ((size_t)b * NGT + wid) * 5;
    const float gx = gp[0] * (float)GS;
    const float gy = gp[1] * (float)GS;
    const float gw = gp[2] * (float)GS;
    const float gh = gp[3] * (float)GS;
    const int   cls = (int)gp[4];

    int gi = (int)gx; gi = min(max(gi, 0), GS - 1);
    int gj = (int)gy; gj = min(max(gj, 0), GS - 1);

    const float gx1 = gx - gw / 2.0f, gy1 = gy - gh / 2.0f;
    const float gx2 = gx + gw / 2.0f, gy2 = gy + gh / 2.0f;
    const float area_g = (gx2 - gx1) * (gy2 - gy1);

    // ---- anchor probes: lane a (a<3) handles anchor a --------------------
    const float ancw = (lane == 0) ? 1.25f  : (lane == 1) ? 2.0f  : 4.125f;
    const float anch = (lane == 0) ? 1.625f : (lane == 1) ? 3.75f : 2.875f;

    float iou = -INFINITY;
    if (lane < NA) {
        const float* xp = x + (size_t)(b * NA + lane) * NATTR * PLANE
                            + (size_t)gj * GS + gi;
        const float txp = xp[0];
        const float typ = xp[PLANE];
        const float twp = xp[2 * PLANE];
        const float thp = xp[3 * PLANE];

        const float bx = sigmoidf(txp) + (float)gi;
        const float by = sigmoidf(typ) + (float)gj;
        const float bw = expf(twp) * ancw;
        const float bh = expf(thp) * anch;

        const float px1 = bx - bw / 2.0f, py1 = by - bh / 2.0f;
        const float px2 = bx + bw / 2.0f, py2 = by + bh / 2.0f;

        const float ix1 = fmaxf(px1, gx1), iy1 = fmaxf(py1, gy1);
        const float ix2 = fminf(px2, gx2), iy2 = fminf(py2, gy2);
        const float inter = fmaxf(ix2 - ix1, 0.0f) * fmaxf(iy2 - iy1, 0.0f);
        const float area_p = (px2 - px1) * (py2 - py1);
        iou = inter / (area_p + area_g - inter + 1e-16f);
    }

    // argmax over 3 anchors (first max wins -> strict >)
    const float i0 = __shfl_sync(0xffffffffu, iou, 0);
    const float i1 = __shfl_sync(0xffffffffu, iou, 1);
    const float i2 = __shfl_sync(0xffffffffu, iou, 2);
    int   best_a   = 0;
    float best_iou = i0;
    if (i1 > best_iou) { best_iou = i1; best_a = 1; }
    if (i2 > best_iou) { best_iou = i2; best_a = 2; }

    const int lin = ((b * NA + best_a) * GS + gj) * GS + gi;

    // ---- issue phase-2 loads NOW; latency hides behind the barrier -------
    const float* base = x + (size_t)(lin / PLANE) * NATTR * PLANE
                          + (lin % PLANE);
    float attr = 0.0f;
    if (lane < 5)       attr = base[(size_t)lane * PLANE];
    else if (lane == 5) attr = base[(size_t)(5 + cls) * PLANE];

    const float v0 = base[(size_t)(5 + lane) * PLANE];
    const float v1 = base[(size_t)(5 + lane + 32) * PLANE];
    const float v2 = (lane < NC - 64) ? base[(size_t)(5 + lane + 64) * PLANE]
                                      : -INFINITY;

    // ---- intra-batch dedup (collisions impossible across batches) --------
    if (lane == 0) s_lin[wid] = lin;
    __syncthreads();

    // JAX scatter .set -> last flat index wins: warp wid loses if any
    // later GT in this batch maps to the same cell.
    const int nAfter = NGT - 1 - wid;               // 0..19
    int dup = (lane < nAfter) && (s_lin[wid + 1 + lane] == lin);
    const unsigned dmask = __ballot_sync(0xffffffffu, dup);

    float lx = 0.f, ly = 0.f, lw = 0.f, lh = 0.f;
    float lcls = 0.f, lconf = 0.f, fwin = 0.f;

    if (dmask == 0u) {   // winner
        fwin = 1.0f;

        // warp logsumexp over the 80 class logits
        float m = fmaxf(fmaxf(v0, v1), v2);
        #pragma unroll
        for (int o = 16; o > 0; o >>= 1)
            m = fmaxf(m, __shfl_xor_sync(0xffffffffu, m, o));

        float s = expf(v0 - m) + expf(v1 - m) +
                  ((lane < NC - 64) ? expf(v2 - m) : 0.0f);
        #pragma unroll
        for (int o = 16; o > 0; o >>= 1)
            s += __shfl_xor_sync(0xffffffffu, s, o);

        const float tx = __shfl_sync(0xffffffffu, attr, 0);
        const float ty = __shfl_sync(0xffffffffu, attr, 1);
        const float tw = __shfl_sync(0xffffffffu, attr, 2);
        const float th = __shfl_sync(0xffffffffu, attr, 3);
        const float cf = __shfl_sync(0xffffffffu, attr, 4);
        const float pk = __shfl_sync(0xffffffffu, attr, 5);

        const float ancwB = (best_a == 0) ? 1.25f  : (best_a == 1) ? 2.0f  : 4.125f;
        const float anchB = (best_a == 0) ? 1.625f : (best_a == 1) ? 3.75f : 2.875f;

        const float dx = sigmoidf(tx) - (gx - (float)gi);
        const float dy = sigmoidf(ty) - (gy - (float)gj);
        const float dw = tw - logf(gw / ancwB);
        const float dh = th - logf(gh / anchB);
        const float dc = sigmoidf(cf) * 5.0f - best_iou * 5.0f;

        lx = dx * dx; ly = dy * dy; lw = dw * dw; lh = dh * dh;
        lconf = dc * dc;
        lcls  = (m + logf(s)) - pk;
    }

    // ---- block reduce + last-block finalize ------------------------------
    if (lane == 0) {
        s_red[0][wid] = lx;   s_red[1][wid] = ly;
        s_red[2][wid] = lw;   s_red[3][wid] = lh;
        s_red[4][wid] = lcls; s_red[5][wid] = lconf;
        s_red[6][wid] = fwin;
    }
    __syncthreads();

    if (t < 7) {
        // thread i sums term i across the 20 warps (serial 20-add chain,
        // 7 threads in parallel), then one atomic each.
        float s = 0.0f;
        #pragma unroll
        for (int w = 0; w < WARPS; w++) s += s_red[t][w];
        atomicAdd(&g_acc[t], s);
    }
    __syncthreads();

    if (t == 0) {
        __threadfence();
        const unsigned old = atomicAdd(&g_tickets, 1u);
        if (old == NBLK - 1) {
            volatile float* acc = g_acc;
            const float ax = acc[0], ay = acc[1], aw = acc[2], ah = acc[3];
            const float acls = acc[4], aconf = acc[5], awin = acc[6];
            const int n_obj = (int)(awin + 0.5f);

            out[0] = ax;  out[1] = ay;  out[2] = aw;  out[3] = ah;
            out[4] = (float)((double)(TOTAL_CELLS - n_obj) * (double)logf(80.0f)
                             + (double)acls);
            out[5] = aconf;

            // reset scratch for the next graph replay
            #pragma unroll
            for (int i = 0; i < 7; i++) g_acc[i] = 0.0f;
            g_tickets = 0u;
            __threadfence();
        }
    }
}

} // namespace

extern "C" void kernel_launch(void* const* d_in, const int* in_sizes, int n_in,
                              void* d_out, int out_size)
{
    const float* x  = (const float*)d_in[0];   // (16, 255, 76, 76) f32
    const float* yt = (const float*)d_in[1];   // (16, 20, 5) f32
    float* out = (float*)d_out;                // 6 floats

    yolo_fused_kernel<<<NBLK, NTHR>>>(x, yt, out);
}